// round 15
// baseline (speedup 1.0000x reference)
#include <cuda_runtime.h>
#include <cuda_fp16.h>
#include <cstdint>

#define HH 64
#define WW 64
#define CIN 256
#define XP 76
#define OC2 49
#define KTOT 12544              // 49 taps * 256 ic
#define NQ 49                   // chunks per CTA: 1 tap x 128 ic (this CTA's half)
#define SLAB_BYTES (152 * 256)  // 2 padded rows x 76 cols x 128 ic fp16, swizzled
#define BTILE_BYTES (64 * 256)  // 64 oc x 128 ic fp16, swizzled
#define BRING_OFF (2 * SLAB_BYTES)
#define SMEM_CONV (BRING_OFF + 2 * BTILE_BYTES)   // 110592 -> 2 CTAs/SM
#define GS4 28                  // gather smem row stride in float4 sites
#define SMEM_FW (25088 + 128 * 130 * 4)

// Scratch (device globals: zero-initialized, allocation-free, graph-capturable)
__device__ float4 g_xi[4 * 64 * XP * XP];        // padded x, 4-ch interleaved (gather)
__device__ __half g_xn[4 * XP * XP * CIN];       // NHWC padded fp16 (conv A)
__device__ __half g_w12t[64 * KTOT];             // fused W^T [oc64][tap*256+ic] fp16
__device__ float  g_b12[OC2];                    // fused bias
__device__ float  g_k2[2 * 4 * OC2 * HH * WW];   // partial logits [icq][b][oc][px]

// ---------------- helpers ----------------
__device__ __forceinline__ uint32_t smem_u32(const void* p) {
    uint32_t a;
    asm("{ .reg .u64 t; cvta.to.shared.u64 t, %1; cvt.u32.u64 %0, t; }" : "=r"(a) : "l"(p));
    return a;
}
__device__ __forceinline__ void cp16(uint32_t d, const void* s) {
    asm volatile("cp.async.cg.shared.global [%0], [%1], 16;" :: "r"(d), "l"(s));
}
#define CP_COMMIT() asm volatile("cp.async.commit_group;")
#define CP_WAIT(n)  asm volatile("cp.async.wait_group %0;" :: "n"(n))

__device__ __forceinline__ void mma_f16(float* c, uint32_t a0, uint32_t a1,
                                        uint32_t a2, uint32_t a3,
                                        uint32_t b0, uint32_t b1) {
    asm volatile(
        "mma.sync.aligned.m16n8k16.row.col.f32.f16.f16.f32 "
        "{%0,%1,%2,%3},{%4,%5,%6,%7},{%8,%9},{%0,%1,%2,%3};"
        : "+f"(c[0]), "+f"(c[1]), "+f"(c[2]), "+f"(c[3])
        : "r"(a0), "r"(a1), "r"(a2), "r"(a3), "r"(b0), "r"(b1));
}
__device__ __forceinline__ void ldm4(uint32_t* r, uint32_t addr) {
    asm volatile("ldmatrix.sync.aligned.m8n8.x4.shared.b16 {%0,%1,%2,%3}, [%4];"
        : "=r"(r[0]), "=r"(r[1]), "=r"(r[2]), "=r"(r[3]) : "r"(addr));
}

// ---------------------------------------------------------------------------
// Combined prep: x -> g_xi (4-ch interleaved fp32) and g_xn (NHWC fp16)
// ---------------------------------------------------------------------------
__global__ __launch_bounds__(256) void prep_x(const float* __restrict__ x) {
    const int h = blockIdx.x, b = blockIdx.y;
    __half* outr = g_xn + (((size_t)b * XP + (h + 6))) * XP * CIN;
    __shared__ float sm[128 * 65];
    for (int half_i = 0; half_i < 2; half_i++) {
        const int ich = half_i * 128;
        for (int idx = threadIdx.x; idx < 128 * 64; idx += 256) {
            int icl = idx >> 6, w = idx & 63;
            sm[icl * 65 + w] = x[(((size_t)(b * CIN + ich + icl)) * HH + h) * WW + w];
        }
        __syncthreads();
        // NHWC fp16 (conv A)
        for (int idx = threadIdx.x; idx < 64 * 128; idx += 256) {
            int w = idx >> 7, icl = idx & 127;
            outr[(size_t)(w + 6) * CIN + ich + icl] = __float2half_rn(sm[icl * 65 + w]);
        }
        // 4-ch interleaved fp32 (gather): cg local 0..31, ch = cg*4+e
        for (int idx = threadIdx.x; idx < 32 * 64; idx += 256) {
            int cgl = idx >> 6, w = idx & 63;
            float4 v = make_float4(sm[(4 * cgl + 0) * 65 + w],
                                   sm[(4 * cgl + 1) * 65 + w],
                                   sm[(4 * cgl + 2) * 65 + w],
                                   sm[(4 * cgl + 3) * 65 + w]);
            g_xi[(((size_t)(b * 64 + half_i * 32 + cgl)) * XP + (h + 6)) * XP
                 + (w + 6)] = v;
        }
        __syncthreads();
    }
}

// ---------------------------------------------------------------------------
// Fused weights as tiled GEMM (blocks 0..97) + fused bias (block 98).
// ---------------------------------------------------------------------------
__global__ __launch_bounds__(256) void fuse_w(const float* __restrict__ w1,
                                              const float* __restrict__ w2,
                                              const float* __restrict__ b1,
                                              const float* __restrict__ b2) {
    const int tid = threadIdx.x;
    if (blockIdx.x == 98) {                  // bias block
        if (tid < OC2) {
            float s = b2[tid];
#pragma unroll 4
            for (int m = 0; m < 128; m++)
                s = fmaf(w2[tid * 128 + m], b1[m], s);
            g_b12[tid] = s;
        }
        return;
    }
    extern __shared__ float fsm[];
    float* w2s = fsm;
    float* sm  = fsm + OC2 * 128;
    const int k0 = blockIdx.x * 128;

    for (int i = tid; i < OC2 * 128; i += 256) w2s[i] = w2[i];
    for (int i = tid; i < 128 * 128; i += 256) {
        int m = i >> 7, kcl = i & 127;
        sm[m * 130 + kcl] = w1[(size_t)m * KTOT + k0 + kcl];
    }
    __syncthreads();

    const int och = tid >> 6;
    const int kc0 = (tid & 63) * 2;
    const int oc0 = och * 12;
    const int ocn = (och < 3) ? 12 : 13;

    float accx[13], accy[13];
#pragma unroll
    for (int j = 0; j < 13; j++) { accx[j] = 0.f; accy[j] = 0.f; }

#pragma unroll 4
    for (int m = 0; m < 128; m++) {
        const float2 a = *(const float2*)&sm[m * 130 + kc0];
#pragma unroll
        for (int j = 0; j < 13; j++) {
            if (j < ocn) {
                const float wv = w2s[(oc0 + j) * 128 + m];
                accx[j] = fmaf(wv, a.x, accx[j]);
                accy[j] = fmaf(wv, a.y, accy[j]);
            }
        }
    }
#pragma unroll
    for (int j = 0; j < 13; j++) {
        if (j < ocn) {
#pragma unroll
            for (int e = 0; e < 2; e++) {
                const int kp = k0 + kc0 + e;
                const int ic = kp / 49, tap = kp - ic * 49;
                g_w12t[(size_t)(oc0 + j) * KTOT + tap * 256 + ic] =
                    __float2half_rn(e ? accy[j] : accx[j]);
            }
        }
    }
}

// ---------------------------------------------------------------------------
// fp16 mma.sync implicit-GEMM conv, K split across 2 CTAs (ic halves).
// Warp grid 4m x 2k; A loaded once per CTA, k-halves summed in smem epilogue.
// ---------------------------------------------------------------------------
__global__ __launch_bounds__(256, 2) void conv_mma() {
    extern __shared__ __align__(16) char smem[];
    const uint32_t sbase = smem_u32(smem);
    const int tid = threadIdx.x, wid = tid >> 5, lane = tid & 31;
    const int gid = lane >> 2, tg = lane & 3;
    const int hr0 = blockIdx.x * 2, b = blockIdx.y, icq = blockIdx.z;
    const int wk = wid >> 2, wm = wid & 3;
    const int mbase = wm * 32;
    const int icbase = icq * 128;
    const int kub = wk * 8;

    float acc[2][8][4];
#pragma unroll
    for (int mt = 0; mt < 2; mt++)
#pragma unroll
        for (int nt = 0; nt < 8; nt++)
#pragma unroll
            for (int r = 0; r < 4; r++) acc[mt][nt][r] = 0.f;

    const int lhi16 = lane >> 4;
    const int bhi = (lane >> 3) & 1;
    int arow0[2];
    {
        const int rsel = ((lane >> 3) & 1) * 8 + (lane & 7);
#pragma unroll
        for (int mt = 0; mt < 2; mt++)
            arow0[mt] = (mbase >> 6) * 76 + (mbase & 63) + mt * 16 + rsel;
    }
    int brow[4];
#pragma unroll
    for (int ntp = 0; ntp < 4; ntp++)
        brow[ntp] = ntp * 16 + (lane >> 4) * 8 + (lane & 7);

    const __half* xb = g_xn + (size_t)b * XP * XP * CIN;

#define COPY_SLAB(u, slot) do {                                                 \
    const __half* _src = xb + ((size_t)(hr0 + 2 * (u)) * XP) * CIN + icbase;    \
    const uint32_t _dst = sbase + (slot) * SLAB_BYTES;                          \
    for (int _i = tid; _i < 2432; _i += 256) {                                  \
        int _row = _i >> 4, _j = _i & 15;                                       \
        int _pr = _row / 76, _col = _row - _pr * 76;                            \
        cp16(_dst + _row * 256 + ((_j ^ (_row & 7)) << 4),                      \
             _src + ((size_t)_pr * XP + _col) * CIN + _j * 8);                  \
    }                                                                           \
} while (0)

#define COPY_B(q, slot) do {                                                    \
    const __half* _bs = g_w12t + (q) * 256 + icbase;                            \
    const uint32_t _dst = sbase + BRING_OFF + (slot) * BTILE_BYTES;             \
    for (int _i = tid; _i < 1024; _i += 256) {                                  \
        int _oc = _i >> 4, _j = _i & 15;                                        \
        cp16(_dst + _oc * 256 + ((_j ^ (_oc & 7)) << 4),                        \
             _bs + (size_t)_oc * KTOT + _j * 8);                                \
    }                                                                           \
} while (0)

    COPY_SLAB(0, 0); COPY_B(0, 0); CP_COMMIT();

#pragma unroll 1
    for (int q = 0; q < NQ; q++) {
        CP_WAIT(0);
        __syncthreads();
        const int s = q / 7, v = q - s * 7;
        if (v == 0 && s + 1 < 7) COPY_SLAB(s + 1, (s + 1) & 1);
        if (q + 1 < NQ) COPY_B(q + 1, (q + 1) & 1);
        CP_COMMIT();

        const uint32_t Aaddr = sbase + (s & 1) * SLAB_BYTES;
        const uint32_t Baddr = sbase + BRING_OFF + (q & 1) * BTILE_BYTES;
        uint32_t Abase[2], Bbase[4];
        int amask[2], bmask[4];
#pragma unroll
        for (int mt = 0; mt < 2; mt++) {
            const int r = arow0[mt] + 2 * v;
            Abase[mt] = Aaddr + r * 256;
            amask[mt] = r & 7;
        }
#pragma unroll
        for (int ntp = 0; ntp < 4; ntp++) {
            Bbase[ntp] = Baddr + brow[ntp] * 256;
            bmask[ntp] = brow[ntp] & 7;
        }
#pragma unroll
        for (int ks = 0; ks < 4; ks++) {
            const int ua = kub + 2 * ks;
            uint32_t Ar[2][4], Br[4][4];
            ldm4(Ar[0], Abase[0] + (((ua + lhi16) ^ amask[0]) << 4));
            ldm4(Ar[1], Abase[1] + (((ua + lhi16) ^ amask[1]) << 4));
#pragma unroll
            for (int ntp = 0; ntp < 4; ntp++)
                ldm4(Br[ntp], Bbase[ntp] + (((ua + bhi) ^ bmask[ntp]) << 4));
#pragma unroll
            for (int mt = 0; mt < 2; mt++)
#pragma unroll
                for (int nt = 0; nt < 8; nt++)
                    mma_f16(acc[mt][nt], Ar[mt][0], Ar[mt][1], Ar[mt][2], Ar[mt][3],
                            Br[nt >> 1][(nt & 1) * 2], Br[nt >> 1][(nt & 1) * 2 + 1]);
        }
    }

    // ---- epilogue: sum k-halves in smem, then partial logits -> g_k2 -------
    __syncthreads();
    float* lg = (float*)smem;               // [128][66]
    if (wk == 0) {
#pragma unroll
        for (int mt = 0; mt < 2; mt++) {
            const int row0 = mbase + mt * 16 + gid;
#pragma unroll
            for (int nt = 0; nt < 8; nt++) {
                const int col = nt * 8 + tg * 2;
                *(float2*)&lg[row0 * 66 + col] =
                    make_float2(acc[mt][nt][0], acc[mt][nt][1]);
                *(float2*)&lg[(row0 + 8) * 66 + col] =
                    make_float2(acc[mt][nt][2], acc[mt][nt][3]);
            }
        }
    }
    __syncthreads();
    if (wk == 1) {
#pragma unroll
        for (int mt = 0; mt < 2; mt++) {
            const int row0 = mbase + mt * 16 + gid;
#pragma unroll
            for (int nt = 0; nt < 8; nt++) {
                const int col = nt * 8 + tg * 2;
                float2* p0 = (float2*)&lg[row0 * 66 + col];
                float2* p1 = (float2*)&lg[(row0 + 8) * 66 + col];
                float2 v0 = *p0, v1 = *p1;
                v0.x += acc[mt][nt][0]; v0.y += acc[mt][nt][1];
                v1.x += acc[mt][nt][2]; v1.y += acc[mt][nt][3];
                *p0 = v0; *p1 = v1;
            }
        }
    }
    __syncthreads();
    if (tid < 128) {
        const float* p = lg + tid * 66;
        float* dst = g_k2 + ((size_t)(icq * 4 + b) * OC2) * (HH * WW)
                     + (hr0 + (tid >> 6)) * WW + (tid & 63);
#pragma unroll
        for (int k = 0; k < OC2; k++)
            dst[(size_t)k * (HH * WW)] = p[k];
    }
#undef COPY_SLAB
#undef COPY_B
}

// ---------------------------------------------------------------------------
// Gather with fused softmax; x read from 4-ch-interleaved g_xi.
// Inner loop: one LDS.128 per tap. Grid y=4 (8 cg-iters/CTA) for occupancy.
// ---------------------------------------------------------------------------
__global__ __launch_bounds__(256) void gather_kernel(float* __restrict__ out) {
    const int tile = blockIdx.x;                 // 8 h-tiles x 4 w-tiles
    const int h0 = (tile >> 2) * 8, w0 = (tile & 3) * 16;
    const int b = blockIdx.z;
    const int tid = threadIdx.x;
    const int sub = tid >> 7, stid = tid & 127;
    const int rr = stid >> 4, cc = stid & 15;
    const int h = h0 + rr, w = w0 + cc;
    const int cg0 = blockIdx.y * 16 + sub * 8;   // float4 channel-group base

    __shared__ __align__(16) float4 xsm[3][2][20 * GS4];

    // ---- fused softmax: attn[k] from the two ic-partials + bias ----
    float attn[OC2];
    {
        const int pxoff = h * WW + w;
        const float* p0 = g_k2 + ((size_t)(0 * 4 + b) * OC2) * (HH * WW) + pxoff;
        const float* p1 = g_k2 + ((size_t)(1 * 4 + b) * OC2) * (HH * WW) + pxoff;
        float mx = -1e30f;
#pragma unroll
        for (int k = 0; k < OC2; k++) {
            attn[k] = p0[(size_t)k * (HH * WW)] + p1[(size_t)k * (HH * WW)]
                      + __ldg(&g_b12[k]);
            mx = fmaxf(mx, attn[k]);
        }
        float s = 0.f;
#pragma unroll
        for (int k = 0; k < OC2; k++) { attn[k] = __expf(attn[k] - mx); s += attn[k]; }
        const float inv = 1.f / s;
#pragma unroll
        for (int k = 0; k < OC2; k++) attn[k] *= inv;
    }

    uint32_t sb[3];
#pragma unroll
    for (int s = 0; s < 3; s++) sb[s] = smem_u32(&xsm[s][sub][0]);

    const float4* plane0 = g_xi + (((size_t)(b * 64 + cg0)) * XP + h0) * XP + w0;

#define CPG(g, st) do {                                                         \
    const float4* _src = plane0 + (size_t)(g) * XP * XP;                        \
    for (int _i = stid; _i < 560; _i += 128) {                                  \
        int _r = _i / GS4, _c = _i - _r * GS4;                                  \
        cp16(sb[st] + _i * 16, _src + _r * XP + _c);                            \
    }                                                                           \
} while (0)

    CPG(0, 0); CP_COMMIT();
    CPG(1, 1); CP_COMMIT();

#pragma unroll 1
    for (int g = 0; g < 8; g++) {
        CP_WAIT(1);
        __syncthreads();
        if (g + 2 < 8) { CPG(g + 2, (g + 2) % 3); }
        CP_COMMIT();

        const float4* xs = &xsm[g % 3][sub][0];
        float o0 = 0.f, o1 = 0.f, o2 = 0.f, o3 = 0.f;
#pragma unroll
        for (int u = 0; u < 7; u++)
#pragma unroll
            for (int v = 0; v < 7; v++) {
                const float4 xv = xs[(rr + 2 * u) * GS4 + cc + 2 * v];
                const float a = attn[u * 7 + v];
                o0 = fmaf(a, xv.x, o0);
                o1 = fmaf(a, xv.y, o1);
                o2 = fmaf(a, xv.z, o2);
                o3 = fmaf(a, xv.w, o3);
            }
        float* dst = out + (((size_t)(b * CIN + (cg0 + g) * 4)) * HH + h) * WW + w;
        dst[0] = o0;
        dst[HH * WW] = o1;
        dst[2 * HH * WW] = o2;
        dst[3 * HH * WW] = o3;
    }
#undef CPG
}

// ---------------------------------------------------------------------------
extern "C" void kernel_launch(void* const* d_in, const int* in_sizes, int n_in,
                              void* d_out, int out_size)
{
    const float* x  = (const float*)d_in[0];
    const float* w1 = (const float*)d_in[1];
    const float* b1 = (const float*)d_in[2];
    const float* w2 = (const float*)d_in[3];
    const float* b2 = (const float*)d_in[4];
    float* out = (float*)d_out;

    cudaFuncSetAttribute(conv_mma, cudaFuncAttributeMaxDynamicSharedMemorySize,
                         SMEM_CONV);
    cudaFuncSetAttribute(fuse_w, cudaFuncAttributeMaxDynamicSharedMemorySize,
                         SMEM_FW);

    prep_x<<<dim3(HH, 4), 256>>>(x);
    fuse_w<<<99, 256, SMEM_FW>>>(w1, w2, b1, b2);
    conv_mma<<<dim3(32, 4, 2), 256, SMEM_CONV>>>();
    gather_kernel<<<dim3(32, 4, 4), 256>>>(out);
}

// round 16
// speedup vs baseline: 1.0722x; 1.0722x over previous
#include <cuda_runtime.h>
#include <cuda_fp16.h>
#include <cstdint>

#define HH 64
#define WW 64
#define CIN 256
#define XP 76
#define OC2 49
#define KTOT 12544              // 49 taps * 256 ic
#define NQ 49                   // chunks per CTA: 1 tap x 128 ic (this CTA's half)
#define SLAB_BYTES (152 * 256)  // 2 padded rows x 76 cols x 128 ic fp16, swizzled
#define BTILE_BYTES (64 * 256)  // 64 oc x 128 ic fp16, swizzled
#define BRING_OFF (2 * SLAB_BYTES)
#define SMEM_CONV (BRING_OFF + 2 * BTILE_BYTES)   // 110592 -> 2 CTAs/SM
#define GS4 28                  // gather smem row stride in float4 sites
#define SMEM_PREP (25088 + 128 * 130 * 4)         // fuse path: w2s + w1 tile

// Scratch (device globals: zero-initialized, allocation-free, graph-capturable)
__device__ float4 g_xi[4 * 64 * XP * XP];        // padded x, 4-ch interleaved (gather)
__device__ __half g_xn[4 * XP * XP * CIN];       // NHWC padded fp16 (conv A)
__device__ __half g_w12t[64 * KTOT];             // fused W^T [oc64][tap*256+ic] fp16
__device__ float  g_b12[OC2];                    // fused bias
__device__ float  g_k2[2 * 4 * OC2 * HH * WW];   // partial logits [icq][b][oc][px]

// ---------------- helpers ----------------
__device__ __forceinline__ uint32_t smem_u32(const void* p) {
    uint32_t a;
    asm("{ .reg .u64 t; cvta.to.shared.u64 t, %1; cvt.u32.u64 %0, t; }" : "=r"(a) : "l"(p));
    return a;
}
__device__ __forceinline__ void cp16(uint32_t d, const void* s) {
    asm volatile("cp.async.cg.shared.global [%0], [%1], 16;" :: "r"(d), "l"(s));
}
#define CP_COMMIT() asm volatile("cp.async.commit_group;")
#define CP_WAIT(n)  asm volatile("cp.async.wait_group %0;" :: "n"(n))

__device__ __forceinline__ void mma_f16(float* c, uint32_t a0, uint32_t a1,
                                        uint32_t a2, uint32_t a3,
                                        uint32_t b0, uint32_t b1) {
    asm volatile(
        "mma.sync.aligned.m16n8k16.row.col.f32.f16.f16.f32 "
        "{%0,%1,%2,%3},{%4,%5,%6,%7},{%8,%9},{%0,%1,%2,%3};"
        : "+f"(c[0]), "+f"(c[1]), "+f"(c[2]), "+f"(c[3])
        : "r"(a0), "r"(a1), "r"(a2), "r"(a3), "r"(b0), "r"(b1));
}
__device__ __forceinline__ void ldm4(uint32_t* r, uint32_t addr) {
    asm volatile("ldmatrix.sync.aligned.m8n8.x4.shared.b16 {%0,%1,%2,%3}, [%4];"
        : "=r"(r[0]), "=r"(r[1]), "=r"(r[2]), "=r"(r[3]) : "r"(addr));
}

// ---------------------------------------------------------------------------
// Merged prep: blocks [0,99) fuse weights (+bias at 98), blocks [99,355) pad x.
// One launch; independent work overlaps on-chip.
// ---------------------------------------------------------------------------
__global__ __launch_bounds__(256) void prep_all(const float* __restrict__ x,
                                                const float* __restrict__ w1,
                                                const float* __restrict__ w2,
                                                const float* __restrict__ b1,
                                                const float* __restrict__ b2) {
    extern __shared__ float fsm[];
    const int tid = threadIdx.x;

    if (blockIdx.x < 99) {
        // ----------------- fuse_w path -----------------
        if (blockIdx.x == 98) {              // bias block
            if (tid < OC2) {
                float s = b2[tid];
#pragma unroll 4
                for (int m = 0; m < 128; m++)
                    s = fmaf(w2[tid * 128 + m], b1[m], s);
                g_b12[tid] = s;
            }
            return;
        }
        float* w2s = fsm;
        float* sm  = fsm + OC2 * 128;
        const int k0 = blockIdx.x * 128;

        for (int i = tid; i < OC2 * 128; i += 256) w2s[i] = w2[i];
        for (int i = tid; i < 128 * 128; i += 256) {
            int m = i >> 7, kcl = i & 127;
            sm[m * 130 + kcl] = w1[(size_t)m * KTOT + k0 + kcl];
        }
        __syncthreads();

        const int och = tid >> 6;
        const int kc0 = (tid & 63) * 2;
        const int oc0 = och * 12;
        const int ocn = (och < 3) ? 12 : 13;

        float accx[13], accy[13];
#pragma unroll
        for (int j = 0; j < 13; j++) { accx[j] = 0.f; accy[j] = 0.f; }

#pragma unroll 4
        for (int m = 0; m < 128; m++) {
            const float2 a = *(const float2*)&sm[m * 130 + kc0];
#pragma unroll
            for (int j = 0; j < 13; j++) {
                if (j < ocn) {
                    const float wv = w2s[(oc0 + j) * 128 + m];
                    accx[j] = fmaf(wv, a.x, accx[j]);
                    accy[j] = fmaf(wv, a.y, accy[j]);
                }
            }
        }
#pragma unroll
        for (int j = 0; j < 13; j++) {
            if (j < ocn) {
#pragma unroll
                for (int e = 0; e < 2; e++) {
                    const int kp = k0 + kc0 + e;
                    const int ic = kp / 49, tap = kp - ic * 49;
                    g_w12t[(size_t)(oc0 + j) * KTOT + tap * 256 + ic] =
                        __float2half_rn(e ? accy[j] : accx[j]);
                }
            }
        }
        return;
    }

    // ----------------- prep_x path -----------------
    const int pb = blockIdx.x - 99;
    const int h = pb & 63, b = pb >> 6;
    __half* outr = g_xn + (((size_t)b * XP + (h + 6))) * XP * CIN;
    float* sm = fsm;                          // [128][65]
    for (int half_i = 0; half_i < 2; half_i++) {
        const int ich = half_i * 128;
        for (int idx = tid; idx < 128 * 64; idx += 256) {
            int icl = idx >> 6, w = idx & 63;
            sm[icl * 65 + w] = x[(((size_t)(b * CIN + ich + icl)) * HH + h) * WW + w];
        }
        __syncthreads();
        // NHWC fp16 (conv A)
        for (int idx = tid; idx < 64 * 128; idx += 256) {
            int w = idx >> 7, icl = idx & 127;
            outr[(size_t)(w + 6) * CIN + ich + icl] = __float2half_rn(sm[icl * 65 + w]);
        }
        // 4-ch interleaved fp32 (gather)
        for (int idx = tid; idx < 32 * 64; idx += 256) {
            int cgl = idx >> 6, w = idx & 63;
            float4 v = make_float4(sm[(4 * cgl + 0) * 65 + w],
                                   sm[(4 * cgl + 1) * 65 + w],
                                   sm[(4 * cgl + 2) * 65 + w],
                                   sm[(4 * cgl + 3) * 65 + w]);
            g_xi[(((size_t)(b * 64 + half_i * 32 + cgl)) * XP + (h + 6)) * XP
                 + (w + 6)] = v;
        }
        __syncthreads();
    }
}

// ---------------------------------------------------------------------------
// fp16 mma.sync implicit-GEMM conv, K split across 2 CTAs (ic halves).
// Warp grid 4m x 2k; A loaded once per CTA, k-halves summed in smem epilogue.
// ---------------------------------------------------------------------------
__global__ __launch_bounds__(256, 2) void conv_mma() {
    extern __shared__ __align__(16) char smem[];
    const uint32_t sbase = smem_u32(smem);
    const int tid = threadIdx.x, wid = tid >> 5, lane = tid & 31;
    const int gid = lane >> 2, tg = lane & 3;
    const int hr0 = blockIdx.x * 2, b = blockIdx.y, icq = blockIdx.z;
    const int wk = wid >> 2, wm = wid & 3;
    const int mbase = wm * 32;
    const int icbase = icq * 128;
    const int kub = wk * 8;

    float acc[2][8][4];
#pragma unroll
    for (int mt = 0; mt < 2; mt++)
#pragma unroll
        for (int nt = 0; nt < 8; nt++)
#pragma unroll
            for (int r = 0; r < 4; r++) acc[mt][nt][r] = 0.f;

    const int lhi16 = lane >> 4;
    const int bhi = (lane >> 3) & 1;
    int arow0[2];
    {
        const int rsel = ((lane >> 3) & 1) * 8 + (lane & 7);
#pragma unroll
        for (int mt = 0; mt < 2; mt++)
            arow0[mt] = (mbase >> 6) * 76 + (mbase & 63) + mt * 16 + rsel;
    }
    int brow[4];
#pragma unroll
    for (int ntp = 0; ntp < 4; ntp++)
        brow[ntp] = ntp * 16 + (lane >> 4) * 8 + (lane & 7);

    const __half* xb = g_xn + (size_t)b * XP * XP * CIN;

#define COPY_SLAB(u, slot) do {                                                 \
    const __half* _src = xb + ((size_t)(hr0 + 2 * (u)) * XP) * CIN + icbase;    \
    const uint32_t _dst = sbase + (slot) * SLAB_BYTES;                          \
    for (int _i = tid; _i < 2432; _i += 256) {                                  \
        int _row = _i >> 4, _j = _i & 15;                                       \
        int _pr = _row / 76, _col = _row - _pr * 76;                            \
        cp16(_dst + _row * 256 + ((_j ^ (_row & 7)) << 4),                      \
             _src + ((size_t)_pr * XP + _col) * CIN + _j * 8);                  \
    }                                                                           \
} while (0)

#define COPY_B(q, slot) do {                                                    \
    const __half* _bs = g_w12t + (q) * 256 + icbase;                            \
    const uint32_t _dst = sbase + BRING_OFF + (slot) * BTILE_BYTES;             \
    for (int _i = tid; _i < 1024; _i += 256) {                                  \
        int _oc = _i >> 4, _j = _i & 15;                                        \
        cp16(_dst + _oc * 256 + ((_j ^ (_oc & 7)) << 4),                        \
             _bs + (size_t)_oc * KTOT + _j * 8);                                \
    }                                                                           \
} while (0)

    COPY_SLAB(0, 0); COPY_B(0, 0); CP_COMMIT();

#pragma unroll 1
    for (int q = 0; q < NQ; q++) {
        CP_WAIT(0);
        __syncthreads();
        const int s = q / 7, v = q - s * 7;
        if (v == 0 && s + 1 < 7) COPY_SLAB(s + 1, (s + 1) & 1);
        if (q + 1 < NQ) COPY_B(q + 1, (q + 1) & 1);
        CP_COMMIT();

        const uint32_t Aaddr = sbase + (s & 1) * SLAB_BYTES;
        const uint32_t Baddr = sbase + BRING_OFF + (q & 1) * BTILE_BYTES;
        uint32_t Abase[2], Bbase[4];
        int amask[2], bmask[4];
#pragma unroll
        for (int mt = 0; mt < 2; mt++) {
            const int r = arow0[mt] + 2 * v;
            Abase[mt] = Aaddr + r * 256;
            amask[mt] = r & 7;
        }
#pragma unroll
        for (int ntp = 0; ntp < 4; ntp++) {
            Bbase[ntp] = Baddr + brow[ntp] * 256;
            bmask[ntp] = brow[ntp] & 7;
        }
#pragma unroll
        for (int ks = 0; ks < 4; ks++) {
            const int ua = kub + 2 * ks;
            uint32_t Ar[2][4], Br[4][4];
            ldm4(Ar[0], Abase[0] + (((ua + lhi16) ^ amask[0]) << 4));
            ldm4(Ar[1], Abase[1] + (((ua + lhi16) ^ amask[1]) << 4));
#pragma unroll
            for (int ntp = 0; ntp < 4; ntp++)
                ldm4(Br[ntp], Bbase[ntp] + (((ua + bhi) ^ bmask[ntp]) << 4));
#pragma unroll
            for (int mt = 0; mt < 2; mt++)
#pragma unroll
                for (int nt = 0; nt < 8; nt++)
                    mma_f16(acc[mt][nt], Ar[mt][0], Ar[mt][1], Ar[mt][2], Ar[mt][3],
                            Br[nt >> 1][(nt & 1) * 2], Br[nt >> 1][(nt & 1) * 2 + 1]);
        }
    }

    // ---- epilogue: sum k-halves in smem, then partial logits -> g_k2 -------
    __syncthreads();
    float* lg = (float*)smem;               // [128][66]
    if (wk == 0) {
#pragma unroll
        for (int mt = 0; mt < 2; mt++) {
            const int row0 = mbase + mt * 16 + gid;
#pragma unroll
            for (int nt = 0; nt < 8; nt++) {
                const int col = nt * 8 + tg * 2;
                *(float2*)&lg[row0 * 66 + col] =
                    make_float2(acc[mt][nt][0], acc[mt][nt][1]);
                *(float2*)&lg[(row0 + 8) * 66 + col] =
                    make_float2(acc[mt][nt][2], acc[mt][nt][3]);
            }
        }
    }
    __syncthreads();
    if (wk == 1) {
#pragma unroll
        for (int mt = 0; mt < 2; mt++) {
            const int row0 = mbase + mt * 16 + gid;
#pragma unroll
            for (int nt = 0; nt < 8; nt++) {
                const int col = nt * 8 + tg * 2;
                float2* p0 = (float2*)&lg[row0 * 66 + col];
                float2* p1 = (float2*)&lg[(row0 + 8) * 66 + col];
                float2 v0 = *p0, v1 = *p1;
                v0.x += acc[mt][nt][0]; v0.y += acc[mt][nt][1];
                v1.x += acc[mt][nt][2]; v1.y += acc[mt][nt][3];
                *p0 = v0; *p1 = v1;
            }
        }
    }
    __syncthreads();
    if (tid < 128) {
        const float* p = lg + tid * 66;
        float* dst = g_k2 + ((size_t)(icq * 4 + b) * OC2) * (HH * WW)
                     + (hr0 + (tid >> 6)) * WW + (tid & 63);
#pragma unroll
        for (int k = 0; k < OC2; k++)
            dst[(size_t)k * (HH * WW)] = p[k];
    }
#undef COPY_SLAB
#undef COPY_B
}

// ---------------------------------------------------------------------------
// Gather with fused softmax; x read from 4-ch-interleaved g_xi.
// Inner loop: one LDS.128 per tap (4 channels at once). R14 config.
// ---------------------------------------------------------------------------
__global__ __launch_bounds__(256) void gather_kernel(float* __restrict__ out) {
    const int tile = blockIdx.x;                 // 8 h-tiles x 4 w-tiles
    const int h0 = (tile >> 2) * 8, w0 = (tile & 3) * 16;
    const int b = blockIdx.z;
    const int tid = threadIdx.x;
    const int sub = tid >> 7, stid = tid & 127;
    const int rr = stid >> 4, cc = stid & 15;
    const int h = h0 + rr, w = w0 + cc;
    const int cg0 = blockIdx.y * 32 + sub * 16;  // float4 channel-group base

    __shared__ __align__(16) float4 xsm[3][2][20 * GS4];

    // ---- fused softmax: attn[k] from the two ic-partials + bias ----
    float attn[OC2];
    {
        const int pxoff = h * WW + w;
        const float* p0 = g_k2 + ((size_t)(0 * 4 + b) * OC2) * (HH * WW) + pxoff;
        const float* p1 = g_k2 + ((size_t)(1 * 4 + b) * OC2) * (HH * WW) + pxoff;
        float mx = -1e30f;
#pragma unroll
        for (int k = 0; k < OC2; k++) {
            attn[k] = p0[(size_t)k * (HH * WW)] + p1[(size_t)k * (HH * WW)]
                      + __ldg(&g_b12[k]);
            mx = fmaxf(mx, attn[k]);
        }
        float s = 0.f;
#pragma unroll
        for (int k = 0; k < OC2; k++) { attn[k] = __expf(attn[k] - mx); s += attn[k]; }
        const float inv = 1.f / s;
#pragma unroll
        for (int k = 0; k < OC2; k++) attn[k] *= inv;
    }

    uint32_t sb[3];
#pragma unroll
    for (int s = 0; s < 3; s++) sb[s] = smem_u32(&xsm[s][sub][0]);

    const float4* plane0 = g_xi + (((size_t)(b * 64 + cg0)) * XP + h0) * XP + w0;

#define CPG(g, st) do {                                                         \
    const float4* _src = plane0 + (size_t)(g) * XP * XP;                        \
    for (int _i = stid; _i < 560; _i += 128) {                                  \
        int _r = _i / GS4, _c = _i - _r * GS4;                                  \
        cp16(sb[st] + _i * 16, _src + _r * XP + _c);                            \
    }                                                                           \
} while (0)

    CPG(0, 0); CP_COMMIT();
    CPG(1, 1); CP_COMMIT();

#pragma unroll 1
    for (int g = 0; g < 16; g++) {
        CP_WAIT(1);
        __syncthreads();
        if (g + 2 < 16) { CPG(g + 2, (g + 2) % 3); }
        CP_COMMIT();

        const float4* xs = &xsm[g % 3][sub][0];
        float o0 = 0.f, o1 = 0.f, o2 = 0.f, o3 = 0.f;
#pragma unroll
        for (int u = 0; u < 7; u++)
#pragma unroll
            for (int v = 0; v < 7; v++) {
                const float4 xv = xs[(rr + 2 * u) * GS4 + cc + 2 * v];
                const float a = attn[u * 7 + v];
                o0 = fmaf(a, xv.x, o0);
                o1 = fmaf(a, xv.y, o1);
                o2 = fmaf(a, xv.z, o2);
                o3 = fmaf(a, xv.w, o3);
            }
        float* dst = out + (((size_t)(b * CIN + (cg0 + g) * 4)) * HH + h) * WW + w;
        dst[0] = o0;
        dst[HH * WW] = o1;
        dst[2 * HH * WW] = o2;
        dst[3 * HH * WW] = o3;
    }
#undef CPG
}

// ---------------------------------------------------------------------------
extern "C" void kernel_launch(void* const* d_in, const int* in_sizes, int n_in,
                              void* d_out, int out_size)
{
    const float* x  = (const float*)d_in[0];
    const float* w1 = (const float*)d_in[1];
    const float* b1 = (const float*)d_in[2];
    const float* w2 = (const float*)d_in[3];
    const float* b2 = (const float*)d_in[4];
    float* out = (float*)d_out;

    cudaFuncSetAttribute(conv_mma, cudaFuncAttributeMaxDynamicSharedMemorySize,
                         SMEM_CONV);
    cudaFuncSetAttribute(prep_all, cudaFuncAttributeMaxDynamicSharedMemorySize,
                         SMEM_PREP);

    prep_all<<<355, 256, SMEM_PREP>>>(x, w1, w2, b1, b2);
    conv_mma<<<dim3(32, 4, 2), 256, SMEM_CONV>>>();
    gather_kernel<<<dim3(32, 2, 4), 256>>>(out);
}

// round 17
// speedup vs baseline: 1.0999x; 1.0258x over previous
#include <cuda_runtime.h>
#include <cuda_fp16.h>
#include <cstdint>

#define HH 64
#define WW 64
#define CIN 256
#define XP 76
#define OC2 49
#define KTOT 12544              // 49 taps * 256 ic = 196 * 64
#define NQ 49                   // chunks per CTA: 1 tap x 128 ic (this CTA's half)
#define SLAB_BYTES (152 * 256)  // 2 padded rows x 76 cols x 128 ic fp16, swizzled
#define BTILE_BYTES (64 * 256)  // 64 oc x 128 ic fp16, swizzled
#define BRING_OFF (2 * SLAB_BYTES)
#define SMEM_CONV (BRING_OFF + 2 * BTILE_BYTES)   // 110592 -> 2 CTAs/SM
#define GS4 28                  // gather smem row stride in float4 sites
#define SMEM_PREP (25088 + 128 * 66 * 4)          // 58880 -> 3 CTAs/SM

// Scratch (device globals: zero-initialized, allocation-free, graph-capturable)
__device__ float4 g_xi[4 * 64 * XP * XP];        // padded x, 4-ch interleaved (gather)
__device__ __half g_xn[4 * XP * XP * CIN];       // NHWC padded fp16 (conv A)
__device__ __half g_w12t[64 * KTOT];             // fused W^T [oc64][tap*256+ic] fp16
__device__ float  g_b12[OC2];                    // fused bias
__device__ float  g_k2[2 * 4 * OC2 * HH * WW];   // partial logits [icq][b][oc][px]

// ---------------- helpers ----------------
__device__ __forceinline__ uint32_t smem_u32(const void* p) {
    uint32_t a;
    asm("{ .reg .u64 t; cvta.to.shared.u64 t, %1; cvt.u32.u64 %0, t; }" : "=r"(a) : "l"(p));
    return a;
}
__device__ __forceinline__ void cp16(uint32_t d, const void* s) {
    asm volatile("cp.async.cg.shared.global [%0], [%1], 16;" :: "r"(d), "l"(s));
}
#define CP_COMMIT() asm volatile("cp.async.commit_group;")
#define CP_WAIT(n)  asm volatile("cp.async.wait_group %0;" :: "n"(n))

__device__ __forceinline__ void mma_f16(float* c, uint32_t a0, uint32_t a1,
                                        uint32_t a2, uint32_t a3,
                                        uint32_t b0, uint32_t b1) {
    asm volatile(
        "mma.sync.aligned.m16n8k16.row.col.f32.f16.f16.f32 "
        "{%0,%1,%2,%3},{%4,%5,%6,%7},{%8,%9},{%0,%1,%2,%3};"
        : "+f"(c[0]), "+f"(c[1]), "+f"(c[2]), "+f"(c[3])
        : "r"(a0), "r"(a1), "r"(a2), "r"(a3), "r"(b0), "r"(b1));
}
__device__ __forceinline__ void ldm4(uint32_t* r, uint32_t addr) {
    asm volatile("ldmatrix.sync.aligned.m8n8.x4.shared.b16 {%0,%1,%2,%3}, [%4];"
        : "=r"(r[0]), "=r"(r[1]), "=r"(r[2]), "=r"(r[3]) : "r"(addr));
}

// ---------------------------------------------------------------------------
// Merged prep: blocks [0,196) fuse weights (64 k'-cols each), 196 = bias,
// blocks [197,453) pad x. 58.9 KB smem -> 3 CTAs/SM.
// ---------------------------------------------------------------------------
__global__ __launch_bounds__(256) void prep_all(const float* __restrict__ x,
                                                const float* __restrict__ w1,
                                                const float* __restrict__ w2,
                                                const float* __restrict__ b1,
                                                const float* __restrict__ b2) {
    extern __shared__ float fsm[];
    const int tid = threadIdx.x;

    if (blockIdx.x < 196) {
        // ----------------- fuse_w path: 64 k'-columns -----------------
        float* w2s = fsm;                     // [49*128]
        float* sm  = fsm + OC2 * 128;         // [128][66]
        const int k0 = blockIdx.x * 64;

        for (int i = tid; i < OC2 * 128; i += 256) w2s[i] = w2[i];
        for (int i = tid; i < 128 * 64; i += 256) {
            int m = i >> 6, kcl = i & 63;
            sm[m * 66 + kcl] = w1[(size_t)m * KTOT + k0 + kcl];
        }
        __syncthreads();

        const int och = tid >> 6;             // 0..3 (uniform per warp)
        const int kc = tid & 63;              // this thread's k'-column
        const int oc0 = och * 12;
        const int ocn = (och < 3) ? 12 : 13;

        float acc[13];
#pragma unroll
        for (int j = 0; j < 13; j++) acc[j] = 0.f;

#pragma unroll 4
        for (int m = 0; m < 128; m++) {
            const float a = sm[m * 66 + kc];
#pragma unroll
            for (int j = 0; j < 13; j++)
                if (j < ocn)
                    acc[j] = fmaf(w2s[(oc0 + j) * 128 + m], a, acc[j]);
        }
        const int kp = k0 + kc;
        const int ic = kp / 49, tap = kp - ic * 49;
#pragma unroll
        for (int j = 0; j < 13; j++)
            if (j < ocn)
                g_w12t[(size_t)(oc0 + j) * KTOT + tap * 256 + ic] =
                    __float2half_rn(acc[j]);
        return;
    }
    if (blockIdx.x == 196) {                  // bias block
        if (tid < OC2) {
            float s = b2[tid];
#pragma unroll 4
            for (int m = 0; m < 128; m++)
                s = fmaf(w2[tid * 128 + m], b1[m], s);
            g_b12[tid] = s;
        }
        return;
    }

    // ----------------- prep_x path -----------------
    const int pb = blockIdx.x - 197;
    const int h = pb & 63, b = pb >> 6;
    __half* outr = g_xn + (((size_t)b * XP + (h + 6))) * XP * CIN;
    float* sm = fsm;                          // [128][65]
    for (int half_i = 0; half_i < 2; half_i++) {
        const int ich = half_i * 128;
        for (int idx = tid; idx < 128 * 64; idx += 256) {
            int icl = idx >> 6, w = idx & 63;
            sm[icl * 65 + w] = x[(((size_t)(b * CIN + ich + icl)) * HH + h) * WW + w];
        }
        __syncthreads();
        // NHWC fp16 (conv A)
        for (int idx = tid; idx < 64 * 128; idx += 256) {
            int w = idx >> 7, icl = idx & 127;
            outr[(size_t)(w + 6) * CIN + ich + icl] = __float2half_rn(sm[icl * 65 + w]);
        }
        // 4-ch interleaved fp32 (gather)
        for (int idx = tid; idx < 32 * 64; idx += 256) {
            int cgl = idx >> 6, w = idx & 63;
            float4 v = make_float4(sm[(4 * cgl + 0) * 65 + w],
                                   sm[(4 * cgl + 1) * 65 + w],
                                   sm[(4 * cgl + 2) * 65 + w],
                                   sm[(4 * cgl + 3) * 65 + w]);
            g_xi[(((size_t)(b * 64 + half_i * 32 + cgl)) * XP + (h + 6)) * XP
                 + (w + 6)] = v;
        }
        __syncthreads();
    }
}

// ---------------------------------------------------------------------------
// fp16 mma.sync implicit-GEMM conv, K split across 2 CTAs (ic halves).
// Warp grid 4m x 2k; A loaded once per CTA, k-halves summed in smem epilogue.
// ---------------------------------------------------------------------------
__global__ __launch_bounds__(256, 2) void conv_mma() {
    extern __shared__ __align__(16) char smem[];
    const uint32_t sbase = smem_u32(smem);
    const int tid = threadIdx.x, wid = tid >> 5, lane = tid & 31;
    const int gid = lane >> 2, tg = lane & 3;
    const int hr0 = blockIdx.x * 2, b = blockIdx.y, icq = blockIdx.z;
    const int wk = wid >> 2, wm = wid & 3;
    const int mbase = wm * 32;
    const int icbase = icq * 128;
    const int kub = wk * 8;

    float acc[2][8][4];
#pragma unroll
    for (int mt = 0; mt < 2; mt++)
#pragma unroll
        for (int nt = 0; nt < 8; nt++)
#pragma unroll
            for (int r = 0; r < 4; r++) acc[mt][nt][r] = 0.f;

    const int lhi16 = lane >> 4;
    const int bhi = (lane >> 3) & 1;
    int arow0[2];
    {
        const int rsel = ((lane >> 3) & 1) * 8 + (lane & 7);
#pragma unroll
        for (int mt = 0; mt < 2; mt++)
            arow0[mt] = (mbase >> 6) * 76 + (mbase & 63) + mt * 16 + rsel;
    }
    int brow[4];
#pragma unroll
    for (int ntp = 0; ntp < 4; ntp++)
        brow[ntp] = ntp * 16 + (lane >> 4) * 8 + (lane & 7);

    const __half* xb = g_xn + (size_t)b * XP * XP * CIN;

#define COPY_SLAB(u, slot) do {                                                 \
    const __half* _src = xb + ((size_t)(hr0 + 2 * (u)) * XP) * CIN + icbase;    \
    const uint32_t _dst = sbase + (slot) * SLAB_BYTES;                          \
    for (int _i = tid; _i < 2432; _i += 256) {                                  \
        int _row = _i >> 4, _j = _i & 15;                                       \
        int _pr = _row / 76, _col = _row - _pr * 76;                            \
        cp16(_dst + _row * 256 + ((_j ^ (_row & 7)) << 4),                      \
             _src + ((size_t)_pr * XP + _col) * CIN + _j * 8);                  \
    }                                                                           \
} while (0)

#define COPY_B(q, slot) do {                                                    \
    const __half* _bs = g_w12t + (q) * 256 + icbase;                            \
    const uint32_t _dst = sbase + BRING_OFF + (slot) * BTILE_BYTES;             \
    for (int _i = tid; _i < 1024; _i += 256) {                                  \
        int _oc = _i >> 4, _j = _i & 15;                                        \
        cp16(_dst + _oc * 256 + ((_j ^ (_oc & 7)) << 4),                        \
             _bs + (size_t)_oc * KTOT + _j * 8);                                \
    }                                                                           \
} while (0)

    COPY_SLAB(0, 0); COPY_B(0, 0); CP_COMMIT();

#pragma unroll 1
    for (int q = 0; q < NQ; q++) {
        CP_WAIT(0);
        __syncthreads();
        const int s = q / 7, v = q - s * 7;
        if (v == 0 && s + 1 < 7) COPY_SLAB(s + 1, (s + 1) & 1);
        if (q + 1 < NQ) COPY_B(q + 1, (q + 1) & 1);
        CP_COMMIT();

        const uint32_t Aaddr = sbase + (s & 1) * SLAB_BYTES;
        const uint32_t Baddr = sbase + BRING_OFF + (q & 1) * BTILE_BYTES;
        uint32_t Abase[2], Bbase[4];
        int amask[2], bmask[4];
#pragma unroll
        for (int mt = 0; mt < 2; mt++) {
            const int r = arow0[mt] + 2 * v;
            Abase[mt] = Aaddr + r * 256;
            amask[mt] = r & 7;
        }
#pragma unroll
        for (int ntp = 0; ntp < 4; ntp++) {
            Bbase[ntp] = Baddr + brow[ntp] * 256;
            bmask[ntp] = brow[ntp] & 7;
        }
#pragma unroll
        for (int ks = 0; ks < 4; ks++) {
            const int ua = kub + 2 * ks;
            uint32_t Ar[2][4], Br[4][4];
            ldm4(Ar[0], Abase[0] + (((ua + lhi16) ^ amask[0]) << 4));
            ldm4(Ar[1], Abase[1] + (((ua + lhi16) ^ amask[1]) << 4));
#pragma unroll
            for (int ntp = 0; ntp < 4; ntp++)
                ldm4(Br[ntp], Bbase[ntp] + (((ua + bhi) ^ bmask[ntp]) << 4));
#pragma unroll
            for (int mt = 0; mt < 2; mt++)
#pragma unroll
                for (int nt = 0; nt < 8; nt++)
                    mma_f16(acc[mt][nt], Ar[mt][0], Ar[mt][1], Ar[mt][2], Ar[mt][3],
                            Br[nt >> 1][(nt & 1) * 2], Br[nt >> 1][(nt & 1) * 2 + 1]);
        }
    }

    // ---- epilogue: sum k-halves in smem, then partial logits -> g_k2 -------
    __syncthreads();
    float* lg = (float*)smem;               // [128][66]
    if (wk == 0) {
#pragma unroll
        for (int mt = 0; mt < 2; mt++) {
            const int row0 = mbase + mt * 16 + gid;
#pragma unroll
            for (int nt = 0; nt < 8; nt++) {
                const int col = nt * 8 + tg * 2;
                *(float2*)&lg[row0 * 66 + col] =
                    make_float2(acc[mt][nt][0], acc[mt][nt][1]);
                *(float2*)&lg[(row0 + 8) * 66 + col] =
                    make_float2(acc[mt][nt][2], acc[mt][nt][3]);
            }
        }
    }
    __syncthreads();
    if (wk == 1) {
#pragma unroll
        for (int mt = 0; mt < 2; mt++) {
            const int row0 = mbase + mt * 16 + gid;
#pragma unroll
            for (int nt = 0; nt < 8; nt++) {
                const int col = nt * 8 + tg * 2;
                float2* p0 = (float2*)&lg[row0 * 66 + col];
                float2* p1 = (float2*)&lg[(row0 + 8) * 66 + col];
                float2 v0 = *p0, v1 = *p1;
                v0.x += acc[mt][nt][0]; v0.y += acc[mt][nt][1];
                v1.x += acc[mt][nt][2]; v1.y += acc[mt][nt][3];
                *p0 = v0; *p1 = v1;
            }
        }
    }
    __syncthreads();
    if (tid < 128) {
        const float* p = lg + tid * 66;
        float* dst = g_k2 + ((size_t)(icq * 4 + b) * OC2) * (HH * WW)
                     + (hr0 + (tid >> 6)) * WW + (tid & 63);
#pragma unroll
        for (int k = 0; k < OC2; k++)
            dst[(size_t)k * (HH * WW)] = p[k];
    }
#undef COPY_SLAB
#undef COPY_B
}

// ---------------------------------------------------------------------------
// Gather with fused softmax; x read from 4-ch-interleaved g_xi.
// Inner loop: one LDS.128 per tap (4 channels at once). R14 config.
// ---------------------------------------------------------------------------
__global__ __launch_bounds__(256) void gather_kernel(float* __restrict__ out) {
    const int tile = blockIdx.x;                 // 8 h-tiles x 4 w-tiles
    const int h0 = (tile >> 2) * 8, w0 = (tile & 3) * 16;
    const int b = blockIdx.z;
    const int tid = threadIdx.x;
    const int sub = tid >> 7, stid = tid & 127;
    const int rr = stid >> 4, cc = stid & 15;
    const int h = h0 + rr, w = w0 + cc;
    const int cg0 = blockIdx.y * 32 + sub * 16;  // float4 channel-group base

    __shared__ __align__(16) float4 xsm[3][2][20 * GS4];

    // ---- fused softmax: attn[k] from the two ic-partials + bias ----
    float attn[OC2];
    {
        const int pxoff = h * WW + w;
        const float* p0 = g_k2 + ((size_t)(0 * 4 + b) * OC2) * (HH * WW) + pxoff;
        const float* p1 = g_k2 + ((size_t)(1 * 4 + b) * OC2) * (HH * WW) + pxoff;
        float mx = -1e30f;
#pragma unroll
        for (int k = 0; k < OC2; k++) {
            attn[k] = p0[(size_t)k * (HH * WW)] + p1[(size_t)k * (HH * WW)]
                      + __ldg(&g_b12[k]);
            mx = fmaxf(mx, attn[k]);
        }
        float s = 0.f;
#pragma unroll
        for (int k = 0; k < OC2; k++) { attn[k] = __expf(attn[k] - mx); s += attn[k]; }
        const float inv = 1.f / s;
#pragma unroll
        for (int k = 0; k < OC2; k++) attn[k] *= inv;
    }

    uint32_t sb[3];
#pragma unroll
    for (int s = 0; s < 3; s++) sb[s] = smem_u32(&xsm[s][sub][0]);

    const float4* plane0 = g_xi + (((size_t)(b * 64 + cg0)) * XP + h0) * XP + w0;

#define CPG(g, st) do {                                                         \
    const float4* _src = plane0 + (size_t)(g) * XP * XP;                        \
    for (int _i = stid; _i < 560; _i += 128) {                                  \
        int _r = _i / GS4, _c = _i - _r * GS4;                                  \
        cp16(sb[st] + _i * 16, _src + _r * XP + _c);                            \
    }                                                                           \
} while (0)

    CPG(0, 0); CP_COMMIT();
    CPG(1, 1); CP_COMMIT();

#pragma unroll 1
    for (int g = 0; g < 16; g++) {
        CP_WAIT(1);
        __syncthreads();
        if (g + 2 < 16) { CPG(g + 2, (g + 2) % 3); }
        CP_COMMIT();

        const float4* xs = &xsm[g % 3][sub][0];
        float o0 = 0.f, o1 = 0.f, o2 = 0.f, o3 = 0.f;
#pragma unroll
        for (int u = 0; u < 7; u++)
#pragma unroll
            for (int v = 0; v < 7; v++) {
                const float4 xv = xs[(rr + 2 * u) * GS4 + cc + 2 * v];
                const float a = attn[u * 7 + v];
                o0 = fmaf(a, xv.x, o0);
                o1 = fmaf(a, xv.y, o1);
                o2 = fmaf(a, xv.z, o2);
                o3 = fmaf(a, xv.w, o3);
            }
        float* dst = out + (((size_t)(b * CIN + (cg0 + g) * 4)) * HH + h) * WW + w;
        dst[0] = o0;
        dst[HH * WW] = o1;
        dst[2 * HH * WW] = o2;
        dst[3 * HH * WW] = o3;
    }
#undef CPG
}

// ---------------------------------------------------------------------------
extern "C" void kernel_launch(void* const* d_in, const int* in_sizes, int n_in,
                              void* d_out, int out_size)
{
    const float* x  = (const float*)d_in[0];
    const float* w1 = (const float*)d_in[1];
    const float* b1 = (const float*)d_in[2];
    const float* w2 = (const float*)d_in[3];
    const float* b2 = (const float*)d_in[4];
    float* out = (float*)d_out;

    cudaFuncSetAttribute(conv_mma, cudaFuncAttributeMaxDynamicSharedMemorySize,
                         SMEM_CONV);
    cudaFuncSetAttribute(prep_all, cudaFuncAttributeMaxDynamicSharedMemorySize,
                         SMEM_PREP);

    prep_all<<<453, 256, SMEM_PREP>>>(x, w1, w2, b1, b2);
    conv_mma<<<dim3(32, 4, 2), 256, SMEM_CONV>>>();
    gather_kernel<<<dim3(32, 2, 4), 256>>>(out);
}